// round 2
// baseline (speedup 1.0000x reference)
#include <cuda_runtime.h>
#include <math.h>

#define BATCH 256
#define SEQ   512
#define HID   256
#define GATE3 768

// Scratch (device globals: the sanctioned allocation-free scratch mechanism)
__device__ float  g_A[SEQ * BATCH * GATE3];   // precomputed x@W_x + bias, layout [t][b][gate*256+j]
__device__ float2 g_Urz[HID * HID];           // [k][j] -> (Wr_h[k][j], Wz_h[k][j]) interleaved

// ---------------------------------------------------------------------------
// Prepack: interleave the hidden-part of Wr and Wz for vectorized LDG.64
// ---------------------------------------------------------------------------
__global__ void prepack_kernel(const float* __restrict__ Wr,
                               const float* __restrict__ Wz) {
    int idx = blockIdx.x * blockDim.x + threadIdx.x;   // 65536
    int k = idx >> 8;
    int j = idx & 255;
    g_Urz[idx] = make_float2(Wr[(256 + k) * 256 + j], Wz[(256 + k) * 256 + j]);
}

// ---------------------------------------------------------------------------
// Precompute: g_A[t*256+b][g*256+j] = x[b,t,:] @ Wg[0:256,:] + bg
// One big GEMM: [131072, 256] @ [256, 768].  BM=128, BN=128, BK=16, 8x8/thread.
// Grid (1024, 6): blockIdx.y selects gate (y/2) and 128-col half (y&1).
// ---------------------------------------------------------------------------
__global__ void __launch_bounds__(256)
precompute_kernel(const float* __restrict__ x,
                  const float* __restrict__ Wr, const float* __restrict__ br,
                  const float* __restrict__ Wz, const float* __restrict__ bz,
                  const float* __restrict__ Wh, const float* __restrict__ bh) {
    __shared__ float As[16][128];
    __shared__ float Bs[16][128];

    const int by = blockIdx.y;
    const float* W;  const float* bias;
    if (by < 2)      { W = Wr; bias = br; }
    else if (by < 4) { W = Wz; bias = bz; }
    else             { W = Wh; bias = bh; }
    const int cb = (by & 1) * 128;           // column offset within the gate
    const int rowBase = blockIdx.x * 128;

    const int tid = threadIdx.x;
    const int tx = tid & 15;                 // 16 col-threads
    const int ty = tid >> 4;                 // 16 row-threads

    float acc[8][8];
#pragma unroll
    for (int i = 0; i < 8; i++)
#pragma unroll
        for (int j = 0; j < 8; j++) acc[i][j] = 0.f;

    for (int k0 = 0; k0 < 256; k0 += 16) {
        // Load A tile (rows of [t*256+b] flattened X): 128x16, transposed into As[k][m]
#pragma unroll
        for (int it = 0; it < 2; it++) {
            int idx = tid * 2 + it;          // 0..511 float4 slots: m(128) x k4(4)
            int m   = idx >> 2;
            int k4  = (idx & 3) * 4;
            int row = rowBase + m;
            int b   = row & 255;
            int t   = row >> 8;
            float4 v = *reinterpret_cast<const float4*>(
                &x[(size_t)b * (SEQ * 256) + t * 256 + k0 + k4]);
            As[k4 + 0][m] = v.x;
            As[k4 + 1][m] = v.y;
            As[k4 + 2][m] = v.z;
            As[k4 + 3][m] = v.w;
        }
        // Load B tile: W[k0+kk][cb + n], 16x128
#pragma unroll
        for (int it = 0; it < 2; it++) {
            int idx = tid * 2 + it;          // kk(16) x n4(32)
            int kk  = idx >> 5;
            int n4  = (idx & 31) * 4;
            *reinterpret_cast<float4*>(&Bs[kk][n4]) =
                *reinterpret_cast<const float4*>(&W[(k0 + kk) * 256 + cb + n4]);
        }
        __syncthreads();

#pragma unroll
        for (int kk = 0; kk < 16; kk++) {
            float4 a0 = *reinterpret_cast<const float4*>(&As[kk][ty * 4]);
            float4 a1 = *reinterpret_cast<const float4*>(&As[kk][64 + ty * 4]);
            float4 b0 = *reinterpret_cast<const float4*>(&Bs[kk][tx * 4]);
            float4 b1 = *reinterpret_cast<const float4*>(&Bs[kk][64 + tx * 4]);
            float av[8] = {a0.x, a0.y, a0.z, a0.w, a1.x, a1.y, a1.z, a1.w};
            float bv[8] = {b0.x, b0.y, b0.z, b0.w, b1.x, b1.y, b1.z, b1.w};
#pragma unroll
            for (int i = 0; i < 8; i++)
#pragma unroll
                for (int j = 0; j < 8; j++) acc[i][j] += av[i] * bv[j];
        }
        __syncthreads();
    }

    // Epilogue: add bias, store float4s
#pragma unroll
    for (int i = 0; i < 8; i++) {
        int m   = (i < 4) ? (ty * 4 + i) : (64 + ty * 4 + (i - 4));
        int row = rowBase + m;
        size_t base = (size_t)row * GATE3 + by * 128;
#pragma unroll
        for (int half = 0; half < 2; half++) {
            int ncol = half * 64 + tx * 4;
            int jj   = (half == 0) ? 0 : 4;
            float4 v;
            v.x = acc[i][jj + 0] + bias[cb + ncol + 0];
            v.y = acc[i][jj + 1] + bias[cb + ncol + 1];
            v.z = acc[i][jj + 2] + bias[cb + ncol + 2];
            v.w = acc[i][jj + 3] + bias[cb + ncol + 3];
            *reinterpret_cast<float4*>(&g_A[base + ncol]) = v;
        }
    }
}

// ---------------------------------------------------------------------------
// Recurrence: 64 blocks x 4 batch rows, 256 threads (thread j = hidden col j),
// loops all 512 timesteps with 2 __syncthreads per step. Output GEMM fused.
// ---------------------------------------------------------------------------
__device__ __forceinline__ float sigmoidf_(float v) {
    return 1.0f / (1.0f + expf(-v));
}

__global__ void __launch_bounds__(256)
gru_recurrence_kernel(const float* __restrict__ Wh,
                      const float* __restrict__ Wo,
                      const float* __restrict__ bo,
                      float* __restrict__ out) {
    __shared__ float hT[256][4];    // hT[k][m] = h[row m][hidden k]
    __shared__ float rhT[256][4];   // (r*h) transposed the same way

    const int j  = threadIdx.x;
    const int b0 = blockIdx.x * 4;
    const float* __restrict__ Uh = Wh + 256 * 256;  // hidden-part rows of Wh

#pragma unroll
    for (int m = 0; m < 4; m++) hT[j][m] = 0.f;
    __syncthreads();

    for (int t = 0; t < SEQ; t++) {
        const float* __restrict__ Arow = g_A + ((size_t)t * 256 + b0) * GATE3;

        // ---- phase 1: r,z pre-activations: h @ [Ur|Uz] ----
        float accr0 = 0.f, accr1 = 0.f, accr2 = 0.f, accr3 = 0.f;
        float accz0 = 0.f, accz1 = 0.f, accz2 = 0.f, accz3 = 0.f;
#pragma unroll 8
        for (int k = 0; k < 256; k++) {
            float2 u  = g_Urz[k * 256 + j];
            float4 h4 = *reinterpret_cast<const float4*>(&hT[k][0]);
            accr0 += h4.x * u.x;  accz0 += h4.x * u.y;
            accr1 += h4.y * u.x;  accz1 += h4.y * u.y;
            accr2 += h4.z * u.x;  accz2 += h4.z * u.y;
            accr3 += h4.w * u.x;  accz3 += h4.w * u.y;
        }

        float r[4], z[4];
        r[0] = sigmoidf_(Arow[0 * GATE3 + j] + accr0);
        r[1] = sigmoidf_(Arow[1 * GATE3 + j] + accr1);
        r[2] = sigmoidf_(Arow[2 * GATE3 + j] + accr2);
        r[3] = sigmoidf_(Arow[3 * GATE3 + j] + accr3);
        z[0] = sigmoidf_(Arow[0 * GATE3 + 256 + j] + accz0);
        z[1] = sigmoidf_(Arow[1 * GATE3 + 256 + j] + accz1);
        z[2] = sigmoidf_(Arow[2 * GATE3 + 256 + j] + accz2);
        z[3] = sigmoidf_(Arow[3 * GATE3 + 256 + j] + accz3);

        // r * h for my hidden column
        float4 hj = *reinterpret_cast<const float4*>(&hT[j][0]);
        float4 rh;
        rh.x = r[0] * hj.x;  rh.y = r[1] * hj.y;
        rh.z = r[2] * hj.z;  rh.w = r[3] * hj.w;
        *reinterpret_cast<float4*>(&rhT[j][0]) = rh;

        __syncthreads();   // (A) rh visible; all phase-1 hT reads complete

        // ---- phase 2: h_cand pre-activation: (r*h) @ Uh ----
        float acch0 = 0.f, acch1 = 0.f, acch2 = 0.f, acch3 = 0.f;
#pragma unroll 8
        for (int k = 0; k < 256; k++) {
            float   u   = Uh[k * 256 + j];
            float4  rh4 = *reinterpret_cast<const float4*>(&rhT[k][0]);
            acch0 += rh4.x * u;
            acch1 += rh4.y * u;
            acch2 += rh4.z * u;
            acch3 += rh4.w * u;
        }

        float hn[4];
        {
            float hc0 = tanhf(Arow[0 * GATE3 + 512 + j] + acch0);
            float hc1 = tanhf(Arow[1 * GATE3 + 512 + j] + acch1);
            float hc2 = tanhf(Arow[2 * GATE3 + 512 + j] + acch2);
            float hc3 = tanhf(Arow[3 * GATE3 + 512 + j] + acch3);
            hn[0] = z[0] * hj.x + (1.f - z[0]) * hc0;
            hn[1] = z[1] * hj.y + (1.f - z[1]) * hc1;
            hn[2] = z[2] * hj.z + (1.f - z[2]) * hc2;
            hn[3] = z[3] * hj.w + (1.f - z[3]) * hc3;
        }
        hT[j][0] = hn[0];
        hT[j][1] = hn[1];
        hT[j][2] = hn[2];
        hT[j][3] = hn[3];

        __syncthreads();   // (B) updated h visible before next step
    }

    // ---- fused output: out[b0+m, j] = h_last[m] @ Wo[:, j] + bo[j] ----
    float o0 = 0.f, o1 = 0.f, o2 = 0.f, o3 = 0.f;
#pragma unroll 8
    for (int k = 0; k < 256; k++) {
        float  w  = Wo[k * 256 + j];
        float4 h4 = *reinterpret_cast<const float4*>(&hT[k][0]);
        o0 += h4.x * w;
        o1 += h4.y * w;
        o2 += h4.z * w;
        o3 += h4.w * w;
    }
    float bj = bo[j];
    out[(b0 + 0) * 256 + j] = o0 + bj;
    out[(b0 + 1) * 256 + j] = o1 + bj;
    out[(b0 + 2) * 256 + j] = o2 + bj;
    out[(b0 + 3) * 256 + j] = o3 + bj;
}

// ---------------------------------------------------------------------------
// Launch
// ---------------------------------------------------------------------------
extern "C" void kernel_launch(void* const* d_in, const int* in_sizes, int n_in,
                              void* d_out, int out_size) {
    const float* x  = (const float*)d_in[0];
    const float* Wr = (const float*)d_in[1];
    const float* br = (const float*)d_in[2];
    const float* Wz = (const float*)d_in[3];
    const float* bz = (const float*)d_in[4];
    const float* Wh = (const float*)d_in[5];
    const float* bh = (const float*)d_in[6];
    const float* Wo = (const float*)d_in[7];
    const float* bo = (const float*)d_in[8];
    float* out = (float*)d_out;

    prepack_kernel<<<256, 256>>>(Wr, Wz);
    precompute_kernel<<<dim3(1024, 6), 256>>>(x, Wr, br, Wz, bz, Wh, bh);
    gru_recurrence_kernel<<<64, 256>>>(Wh, Wo, bo, out);
}

// round 4
// speedup vs baseline: 1.9495x; 1.9495x over previous
#include <cuda_runtime.h>
#include <cstdint>
#include <math.h>

#define BATCH 256
#define SEQ   512
#define HID   256
#define GATE3 768
#define KC    80          // k-rows of Urz cached in smem
// dynamic smem: Uh 128KB + Urz 80KB + hT 4KB + rhT 4KB + z_s 2KB
#define SMEM_BYTES (131072 + KC*1024 + 4096 + 4096 + 2048)

// Scratch (device globals: sanctioned allocation-free scratch)
__device__ float g_A[SEQ * BATCH * GATE3];  // x@W_x + bias, [t][b][gate*256+j]
__device__ float g_Urz_p[HID * 512];        // [k][g*256 + j]: g=0 -> Ur_h, g=1 -> Uz_h

// ---------------------------------------------------------------------------
// helpers: DSMEM remote stores + cluster barrier
// ---------------------------------------------------------------------------
__device__ __forceinline__ uint32_t smem_u32(const void* p) {
    uint32_t a;
    asm("{ .reg .u64 t; cvta.to.shared.u64 t, %1; cvt.u32.u64 %0, t; }"
        : "=r"(a) : "l"(p));
    return a;
}
__device__ __forceinline__ uint32_t mapa_peer(uint32_t addr, uint32_t rank) {
    uint32_t r;
    asm("mapa.shared::cluster.u32 %0, %1, %2;" : "=r"(r) : "r"(addr), "r"(rank));
    return r;
}
__device__ __forceinline__ void st_cluster_v4(uint32_t addr, float4 v) {
    asm volatile("st.shared::cluster.v4.f32 [%0], {%1,%2,%3,%4};"
                 :: "r"(addr), "f"(v.x), "f"(v.y), "f"(v.z), "f"(v.w) : "memory");
}
__device__ __forceinline__ void st_cluster_v2(uint32_t addr, float2 v) {
    asm volatile("st.shared::cluster.v2.f32 [%0], {%1,%2};"
                 :: "r"(addr), "f"(v.x), "f"(v.y) : "memory");
}
__device__ __forceinline__ void cluster_sync_() {
    asm volatile("barrier.cluster.arrive.aligned;" ::: "memory");
    asm volatile("barrier.cluster.wait.aligned;" ::: "memory");
}
__device__ __forceinline__ float sigmoidf_(float v) { return 1.0f / (1.0f + expf(-v)); }

// ---------------------------------------------------------------------------
// Prepack: g_Urz_p[k][g*256+j] = (g==0 ? Wr : Wz)[256+k][j]
// ---------------------------------------------------------------------------
__global__ void prepack_kernel(const float* __restrict__ Wr,
                               const float* __restrict__ Wz) {
    int idx = blockIdx.x * blockDim.x + threadIdx.x;   // 131072
    int k = idx >> 9;
    int c = idx & 511;
    int g = c >> 8;
    int j = c & 255;
    g_Urz_p[idx] = (g == 0) ? Wr[(256 + k) * 256 + j] : Wz[(256 + k) * 256 + j];
}

// ---------------------------------------------------------------------------
// Precompute GEMM: g_A[t*256+b][g*256+j] = x[b,t,:] @ Wg[0:256,:] + bg
// [131072, 256] @ [256, 768], BM=BN=128, BK=16, 8x8 per thread.
// ---------------------------------------------------------------------------
__global__ void __launch_bounds__(256)
precompute_kernel(const float* __restrict__ x,
                  const float* __restrict__ Wr, const float* __restrict__ br,
                  const float* __restrict__ Wz, const float* __restrict__ bz,
                  const float* __restrict__ Wh, const float* __restrict__ bh) {
    __shared__ float As[16][128];
    __shared__ float Bs[16][128];

    const int by = blockIdx.y;
    const float* W;  const float* bias;
    if (by < 2)      { W = Wr; bias = br; }
    else if (by < 4) { W = Wz; bias = bz; }
    else             { W = Wh; bias = bh; }
    const int cb = (by & 1) * 128;
    const int rowBase = blockIdx.x * 128;

    const int tid = threadIdx.x;
    const int tx = tid & 15;
    const int ty = tid >> 4;

    float acc[8][8];
#pragma unroll
    for (int i = 0; i < 8; i++)
#pragma unroll
        for (int j = 0; j < 8; j++) acc[i][j] = 0.f;

    for (int k0 = 0; k0 < 256; k0 += 16) {
#pragma unroll
        for (int it = 0; it < 2; it++) {
            int idx = tid * 2 + it;
            int m   = idx >> 2;
            int k4  = (idx & 3) * 4;
            int row = rowBase + m;
            int b   = row & 255;
            int t   = row >> 8;
            float4 v = *reinterpret_cast<const float4*>(
                &x[(size_t)b * (SEQ * 256) + t * 256 + k0 + k4]);
            As[k4 + 0][m] = v.x;
            As[k4 + 1][m] = v.y;
            As[k4 + 2][m] = v.z;
            As[k4 + 3][m] = v.w;
        }
#pragma unroll
        for (int it = 0; it < 2; it++) {
            int idx = tid * 2 + it;
            int kk  = idx >> 5;
            int n4  = (idx & 31) * 4;
            *reinterpret_cast<float4*>(&Bs[kk][n4]) =
                *reinterpret_cast<const float4*>(&W[(k0 + kk) * 256 + cb + n4]);
        }
        __syncthreads();

#pragma unroll
        for (int kk = 0; kk < 16; kk++) {
            float4 a0 = *reinterpret_cast<const float4*>(&As[kk][ty * 4]);
            float4 a1 = *reinterpret_cast<const float4*>(&As[kk][64 + ty * 4]);
            float4 b0 = *reinterpret_cast<const float4*>(&Bs[kk][tx * 4]);
            float4 b1 = *reinterpret_cast<const float4*>(&Bs[kk][64 + tx * 4]);
            float av[8] = {a0.x, a0.y, a0.z, a0.w, a1.x, a1.y, a1.z, a1.w};
            float bv[8] = {b0.x, b0.y, b0.z, b0.w, b1.x, b1.y, b1.z, b1.w};
#pragma unroll
            for (int i = 0; i < 8; i++)
#pragma unroll
                for (int j = 0; j < 8; j++) acc[i][j] += av[i] * bv[j];
        }
        __syncthreads();
    }

#pragma unroll
    for (int i = 0; i < 8; i++) {
        int m   = (i < 4) ? (ty * 4 + i) : (64 + ty * 4 + (i - 4));
        int row = rowBase + m;
        size_t base = (size_t)row * GATE3 + by * 128;
#pragma unroll
        for (int half = 0; half < 2; half++) {
            int ncol = half * 64 + tx * 4;
            int jj   = (half == 0) ? 0 : 4;
            float4 v;
            v.x = acc[i][jj + 0] + bias[cb + ncol + 0];
            v.y = acc[i][jj + 1] + bias[cb + ncol + 1];
            v.z = acc[i][jj + 2] + bias[cb + ncol + 2];
            v.w = acc[i][jj + 3] + bias[cb + ncol + 3];
            *reinterpret_cast<float4*>(&g_A[base + ncol]) = v;
        }
    }
}

// ---------------------------------------------------------------------------
// Recurrence: 64 clusters x 2 CTAs. Cluster = 4 batch rows; CTA rank q owns
// hidden columns [q*128, q*128+128). 256 threads = (gate g, column j).
// Phase1: thread (g,j) computes gate g pre-act for column jg, all 4 rows.
// Phase2: thread (g,j) computes h_cand/h_new for column jg, rows 2g, 2g+1.
// r*h halves and h halves are exchanged via DSMEM + cluster.sync.
// ---------------------------------------------------------------------------
__global__ void __launch_bounds__(256, 1)
gru_recurrence_kernel(const float* __restrict__ Wh,
                      const float* __restrict__ Wo,
                      const float* __restrict__ bo,
                      float* __restrict__ out) {
    extern __shared__ char smem_raw[];
    float  (*Uh_s)[128] = (float(*)[128])(smem_raw);                      // 128KB
    float*  Urz_s       = (float*)(smem_raw + 131072);                    // KC*1KB
    float4* hT          = (float4*)(smem_raw + 131072 + KC * 1024);       // 4KB
    float4* rhT         = hT + 256;                                       // 4KB
    float4* z_s         = rhT + 256;                                      // 2KB

    const int tid = threadIdx.x;
    const int g   = tid >> 7;          // 0 = r-gate, 1 = z-gate
    const int j   = tid & 127;         // local column
    const int q   = blockIdx.x & 1;    // cluster rank
    const int jg  = q * 128 + j;       // global hidden column
    const int b0  = (blockIdx.x >> 1) * 4;
    const int m0  = 2 * g;             // phase-2 rows

    const float* __restrict__ Uh = Wh + 256 * 256;
    const int colU = g * 256 + jg;     // column into g_Urz_p
    const int cs   = g * 128 + j;      // column into Urz_s

    // ---- preload smem weights ----
    for (int i = tid; i < 256 * 128; i += 256) {
        int k = i >> 7, jj = i & 127;
        Uh_s[k][jj] = Uh[k * 256 + q * 128 + jj];
    }
    for (int i = tid; i < KC * 256; i += 256) {
        int k = i >> 8, c = i & 255;
        Urz_s[i] = g_Urz_p[k * 512 + (c >> 7) * 256 + q * 128 + (c & 127)];
    }
    if (tid < 256) hT[tid] = make_float4(0.f, 0.f, 0.f, 0.f);
    __syncthreads();

    // remote (peer-CTA) smem addresses for my column
    const uint32_t peer      = q ^ 1;
    const uint32_t rhT_rem   = mapa_peer(smem_u32(&rhT[jg]), peer);
    const uint32_t hT_rem    = mapa_peer(smem_u32((float*)&hT[jg] + m0), peer);

    cluster_sync_();

    for (int t = 0; t < SEQ; t++) {
        const float* __restrict__ Arow = g_A + ((size_t)t * 256 + b0) * GATE3;

        // hoist DRAM loads of precomputed activations
        float a_g[4];
#pragma unroll
        for (int m = 0; m < 4; m++) a_g[m] = Arow[m * GATE3 + g * 256 + jg];
        float a_h0 = Arow[(m0 + 0) * GATE3 + 512 + jg];
        float a_h1 = Arow[(m0 + 1) * GATE3 + 512 + jg];

        // ---- phase 1: gate pre-activation  h @ U_g (column jg, 4 rows) ----
        float ac0 = 0.f, ac1 = 0.f, ac2 = 0.f, ac3 = 0.f;
#pragma unroll 8
        for (int k = 0; k < KC; k++) {
            float u = Urz_s[k * 256 + cs];
            float4 h4 = hT[k];
            ac0 += h4.x * u;  ac1 += h4.y * u;
            ac2 += h4.z * u;  ac3 += h4.w * u;
        }
        for (int k0 = KC; k0 < 256; k0 += 8) {
            float u[8];
#pragma unroll
            for (int i = 0; i < 8; i++) u[i] = g_Urz_p[(k0 + i) * 512 + colU];
#pragma unroll
            for (int i = 0; i < 8; i++) {
                float4 h4 = hT[k0 + i];
                ac0 += h4.x * u[i];  ac1 += h4.y * u[i];
                ac2 += h4.z * u[i];  ac3 += h4.w * u[i];
            }
        }

        float4 hj = hT[jg];
        if (g == 0) {
            // r gate -> r*h, exchange to both CTAs
            float4 rh;
            rh.x = sigmoidf_(a_g[0] + ac0) * hj.x;
            rh.y = sigmoidf_(a_g[1] + ac1) * hj.y;
            rh.z = sigmoidf_(a_g[2] + ac2) * hj.z;
            rh.w = sigmoidf_(a_g[3] + ac3) * hj.w;
            rhT[jg] = rh;
            st_cluster_v4(rhT_rem, rh);
        } else {
            // z gate -> local smem only
            float4 zv;
            zv.x = sigmoidf_(a_g[0] + ac0);
            zv.y = sigmoidf_(a_g[1] + ac1);
            zv.z = sigmoidf_(a_g[2] + ac2);
            zv.w = sigmoidf_(a_g[3] + ac3);
            z_s[j] = zv;
        }

        cluster_sync_();   // (A) rh halves visible cluster-wide, z visible locally

        // ---- phase 2: h_cand = tanh(a_h + (r*h) @ Uh) for rows m0, m0+1 ----
        float ah0 = 0.f, ah1 = 0.f;
#pragma unroll 8
        for (int k = 0; k < 256; k++) {
            float u = Uh_s[k][j];
            float2 rh2 = *reinterpret_cast<const float2*>(
                reinterpret_cast<const float*>(&rhT[k]) + m0);
            ah0 += rh2.x * u;
            ah1 += rh2.y * u;
        }

        float2 z2 = *reinterpret_cast<const float2*>(
            reinterpret_cast<const float*>(&z_s[j]) + m0);
        float h_old0 = reinterpret_cast<const float*>(&hj)[m0 + 0];
        float h_old1 = reinterpret_cast<const float*>(&hj)[m0 + 1];

        float hc0 = tanhf(a_h0 + ah0);
        float hc1 = tanhf(a_h1 + ah1);
        float2 hn;
        hn.x = z2.x * h_old0 + (1.f - z2.x) * hc0;
        hn.y = z2.y * h_old1 + (1.f - z2.y) * hc1;

        reinterpret_cast<float*>(&hT[jg])[m0 + 0] = hn.x;
        reinterpret_cast<float*>(&hT[jg])[m0 + 1] = hn.y;
        st_cluster_v2(hT_rem, hn);

        cluster_sync_();   // (B) full updated h visible before next step
    }

    // ---- fused output: out[b0+m, jg] = h_last[m] @ Wo[:, jg] + bo[jg] ----
    // thread (g,j): rows m0, m0+1 for column jg
    float o0 = 0.f, o1 = 0.f;
#pragma unroll 8
    for (int k = 0; k < 256; k++) {
        float w = Wo[k * 256 + jg];
        float2 h2 = *reinterpret_cast<const float2*>(
            reinterpret_cast<const float*>(&hT[k]) + m0);
        o0 += h2.x * w;
        o1 += h2.y * w;
    }
    float bj = bo[jg];
    out[(b0 + m0 + 0) * 256 + jg] = o0 + bj;
    out[(b0 + m0 + 1) * 256 + jg] = o1 + bj;
}

// ---------------------------------------------------------------------------
// Launch
// ---------------------------------------------------------------------------
extern "C" void kernel_launch(void* const* d_in, const int* in_sizes, int n_in,
                              void* d_out, int out_size) {
    const float* x  = (const float*)d_in[0];
    const float* Wr = (const float*)d_in[1];
    const float* br = (const float*)d_in[2];
    const float* Wz = (const float*)d_in[3];
    const float* bz = (const float*)d_in[4];
    const float* Wh = (const float*)d_in[5];
    const float* bh = (const float*)d_in[6];
    const float* Wo = (const float*)d_in[7];
    const float* bo = (const float*)d_in[8];
    float* out = (float*)d_out;

    prepack_kernel<<<512, 256>>>(Wr, Wz);
    precompute_kernel<<<dim3(1024, 6), 256>>>(x, Wr, br, Wz, bz, Wh, bh);

    cudaFuncSetAttribute(gru_recurrence_kernel,
                         cudaFuncAttributeMaxDynamicSharedMemorySize, SMEM_BYTES);

    cudaLaunchConfig_t cfg = {};
    cfg.gridDim  = dim3(128, 1, 1);
    cfg.blockDim = dim3(256, 1, 1);
    cfg.dynamicSmemBytes = SMEM_BYTES;
    cfg.stream = 0;
    cudaLaunchAttribute attrs[1];
    attrs[0].id = cudaLaunchAttributeClusterDimension;
    attrs[0].val.clusterDim.x = 2;
    attrs[0].val.clusterDim.y = 1;
    attrs[0].val.clusterDim.z = 1;
    cfg.attrs = attrs;
    cfg.numAttrs = 1;
    cudaLaunchKernelEx(&cfg, gru_recurrence_kernel, Wh, Wo, bo, out);
}

// round 5
// speedup vs baseline: 3.2615x; 1.6730x over previous
#include <cuda_runtime.h>
#include <cstdint>
#include <math.h>

#define BATCH 256
#define SEQ   512
#define HID   256
#define GATE3 768

// Recurrence smem: Ur(64K) + Uz(64K) + Uh(64K) + hT(8K) + rhT(8K) + z(2K)
#define REC_SMEM_FLOATS (3*16384 + 2048 + 2048 + 512)
#define REC_SMEM_BYTES  (REC_SMEM_FLOATS * 4)     // 215040 B = 210 KB

// Scratch (device global: sanctioned allocation-free scratch)
__device__ float g_A[SEQ * BATCH * GATE3];  // x@W_x + bias, [t][b][gate*256+j]

// ---------------------------------------------------------------------------
// helpers
// ---------------------------------------------------------------------------
__device__ __forceinline__ uint32_t smem_u32(const void* p) {
    uint32_t a;
    asm("{ .reg .u64 t; cvta.to.shared.u64 t, %1; cvt.u32.u64 %0, t; }"
        : "=r"(a) : "l"(p));
    return a;
}
__device__ __forceinline__ uint32_t mapa_peer(uint32_t addr, uint32_t rank) {
    uint32_t r;
    asm("mapa.shared::cluster.u32 %0, %1, %2;" : "=r"(r) : "r"(addr), "r"(rank));
    return r;
}
__device__ __forceinline__ void st_cluster_v4(uint32_t addr, float4 v) {
    asm volatile("st.shared::cluster.v4.f32 [%0], {%1,%2,%3,%4};"
                 :: "r"(addr), "f"(v.x), "f"(v.y), "f"(v.z), "f"(v.w) : "memory");
}
__device__ __forceinline__ void st_cluster_v2(uint32_t addr, float2 v) {
    asm volatile("st.shared::cluster.v2.f32 [%0], {%1,%2};"
                 :: "r"(addr), "f"(v.x), "f"(v.y) : "memory");
}
__device__ __forceinline__ void cluster_sync_() {
    asm volatile("barrier.cluster.arrive.aligned;" ::: "memory");
    asm volatile("barrier.cluster.wait.aligned;" ::: "memory");
}
__device__ __forceinline__ float sigmoidf_(float v) { return 1.0f / (1.0f + expf(-v)); }

// ---- packed f32x2 (Blackwell FFMA2 path) ----
__device__ __forceinline__ unsigned long long packf2(float lo, float hi) {
    unsigned long long r;
    asm("mov.b64 %0, {%1, %2};" : "=l"(r)
        : "r"(__float_as_uint(lo)), "r"(__float_as_uint(hi)));
    return r;
}
__device__ __forceinline__ unsigned long long dupf2(float v) {
    unsigned long long r;
    uint32_t u = __float_as_uint(v);
    asm("mov.b64 %0, {%1, %1};" : "=l"(r) : "r"(u));
    return r;
}
__device__ __forceinline__ void ffma2(unsigned long long& d,
                                      unsigned long long a,
                                      unsigned long long b) {
    asm("fma.rn.f32x2 %0, %1, %2, %0;" : "+l"(d) : "l"(a), "l"(b));
}
__device__ __forceinline__ float2 unpackf2(unsigned long long v) {
    uint32_t lo, hi;
    asm("mov.b64 {%0, %1}, %2;" : "=r"(lo), "=r"(hi) : "l"(v));
    float2 f;
    f.x = __uint_as_float(lo);
    f.y = __uint_as_float(hi);
    return f;
}

// ---------------------------------------------------------------------------
// Precompute GEMM (FFMA2): g_A[t*256+b][g*256+j] = x[b,t,:] @ Wg[0:256,:] + bg
// [131072, 256] @ [256, 768], BM=BN=128, BK=16, 8x8 per thread (as 8x4 f32x2).
// ---------------------------------------------------------------------------
__global__ void __launch_bounds__(256)
precompute_kernel(const float* __restrict__ x,
                  const float* __restrict__ Wr, const float* __restrict__ br,
                  const float* __restrict__ Wz, const float* __restrict__ bz,
                  const float* __restrict__ Wh, const float* __restrict__ bh) {
    __shared__ float As[16][128];
    __shared__ float Bs[16][128];

    const int by = blockIdx.y;
    const float* W;  const float* bias;
    if (by < 2)      { W = Wr; bias = br; }
    else if (by < 4) { W = Wz; bias = bz; }
    else             { W = Wh; bias = bh; }
    const int cb = (by & 1) * 128;
    const int rowBase = blockIdx.x * 128;

    const int tid = threadIdx.x;
    const int tx = tid & 15;
    const int ty = tid >> 4;

    unsigned long long acc2[8][4];
#pragma unroll
    for (int i = 0; i < 8; i++)
#pragma unroll
        for (int j = 0; j < 4; j++) acc2[i][j] = 0ull;

    for (int k0 = 0; k0 < 256; k0 += 16) {
#pragma unroll
        for (int it = 0; it < 2; it++) {
            int idx = tid * 2 + it;
            int m   = idx >> 2;
            int k4  = (idx & 3) * 4;
            int row = rowBase + m;
            int b   = row & 255;
            int t   = row >> 8;
            float4 v = *reinterpret_cast<const float4*>(
                &x[(size_t)b * (SEQ * 256) + t * 256 + k0 + k4]);
            As[k4 + 0][m] = v.x;
            As[k4 + 1][m] = v.y;
            As[k4 + 2][m] = v.z;
            As[k4 + 3][m] = v.w;
        }
#pragma unroll
        for (int it = 0; it < 2; it++) {
            int idx = tid * 2 + it;
            int kk  = idx >> 5;
            int n4  = (idx & 31) * 4;
            *reinterpret_cast<float4*>(&Bs[kk][n4]) =
                *reinterpret_cast<const float4*>(&W[(k0 + kk) * 256 + cb + n4]);
        }
        __syncthreads();

#pragma unroll
        for (int kk = 0; kk < 16; kk++) {
            float4 a0 = *reinterpret_cast<const float4*>(&As[kk][ty * 4]);
            float4 a1 = *reinterpret_cast<const float4*>(&As[kk][64 + ty * 4]);
            float4 b0 = *reinterpret_cast<const float4*>(&Bs[kk][tx * 4]);
            float4 b1 = *reinterpret_cast<const float4*>(&Bs[kk][64 + tx * 4]);
            unsigned long long bp0 = packf2(b0.x, b0.y);
            unsigned long long bp1 = packf2(b0.z, b0.w);
            unsigned long long bp2 = packf2(b1.x, b1.y);
            unsigned long long bp3 = packf2(b1.z, b1.w);
            float av[8] = {a0.x, a0.y, a0.z, a0.w, a1.x, a1.y, a1.z, a1.w};
#pragma unroll
            for (int i = 0; i < 8; i++) {
                unsigned long long ad = dupf2(av[i]);
                ffma2(acc2[i][0], ad, bp0);
                ffma2(acc2[i][1], ad, bp1);
                ffma2(acc2[i][2], ad, bp2);
                ffma2(acc2[i][3], ad, bp3);
            }
        }
        __syncthreads();
    }

#pragma unroll
    for (int i = 0; i < 8; i++) {
        int m   = (i < 4) ? (ty * 4 + i) : (64 + ty * 4 + (i - 4));
        int row = rowBase + m;
        size_t base = (size_t)row * GATE3 + by * 128;
#pragma unroll
        for (int half = 0; half < 2; half++) {
            int ncol = half * 64 + tx * 4;
            float2 p0 = unpackf2(acc2[i][half * 2 + 0]);
            float2 p1 = unpackf2(acc2[i][half * 2 + 1]);
            float4 v;
            v.x = p0.x + bias[cb + ncol + 0];
            v.y = p0.y + bias[cb + ncol + 1];
            v.z = p1.x + bias[cb + ncol + 2];
            v.w = p1.y + bias[cb + ncol + 3];
            *reinterpret_cast<float4*>(&g_A[base + ncol]) = v;
        }
    }
}

// ---------------------------------------------------------------------------
// Recurrence: 32 clusters x 4 CTAs. Cluster = 8 batch rows; CTA rank q owns
// hidden columns [q*64, q*64+64). ALL weights (Ur/Uz/Uh quarters) smem-resident.
// Phase1: thread (g, j, rp): gate g pre-act for col jg, rows rp*4..rp*4+3.
// Phase2: thread (j2, rg): h_cand/h_new for col jg2, rows rg*2, rg*2+1.
// r*h and h are broadcast to all 3 peer CTAs via DSMEM + cluster.sync.
// ---------------------------------------------------------------------------
__global__ void __launch_bounds__(256, 1)
gru_recurrence_kernel(const float* __restrict__ Wr,
                      const float* __restrict__ Wz,
                      const float* __restrict__ Wh,
                      const float* __restrict__ Wo,
                      const float* __restrict__ bo,
                      float* __restrict__ out) {
    extern __shared__ char smem_raw[];
    float* Ur_s = (float*)smem_raw;        // [256][64]
    float* Uz_s = Ur_s + 16384;            // [256][64]
    float* Uh_s = Uz_s + 16384;            // [256][64]
    float* hT   = Uh_s + 16384;            // [256 cols][8 rows]
    float* rhT  = hT + 2048;               // [256 cols][8 rows]
    float* z_s  = rhT + 2048;              // [64 cols][8 rows]

    const int tid = threadIdx.x;
    const int q   = blockIdx.x & 3;                 // cluster rank
    const int b0  = (blockIdx.x >> 2) * 8;          // batch base

    // phase-1 mapping
    const int g   = tid >> 7;                       // 0=r, 1=z
    const int jj  = (tid >> 1) & 63;
    const int rp  = tid & 1;
    const int jg  = q * 64 + jj;
    const int m0  = rp * 4;
    // phase-2 mapping
    const int j2  = tid >> 2;
    const int rg  = tid & 3;
    const int jg2 = q * 64 + j2;
    const int r0  = rg * 2;

    // ---- preload weight quarters (hidden-part rows 256..511, cols q*64..) ----
    for (int i = tid; i < 16384; i += 256) {
        int k = i >> 6, c = i & 63;
        int gidx = (256 + k) * 256 + q * 64 + c;
        Ur_s[i] = Wr[gidx];
        Uz_s[i] = Wz[gidx];
        Uh_s[i] = Wh[gidx];
    }
    for (int i = tid; i < 2048; i += 256) hT[i] = 0.f;
    __syncthreads();

    const float* __restrict__ Ug = g ? Uz_s : Ur_s;

    // remote peer addresses
    const uint32_t rh_loc = smem_u32(&rhT[jg * 8 + m0]);
    const uint32_t h_loc  = smem_u32(&hT[jg2 * 8 + r0]);
    const uint32_t rh_r1 = mapa_peer(rh_loc, q ^ 1);
    const uint32_t rh_r2 = mapa_peer(rh_loc, q ^ 2);
    const uint32_t rh_r3 = mapa_peer(rh_loc, q ^ 3);
    const uint32_t h_r1  = mapa_peer(h_loc, q ^ 1);
    const uint32_t h_r2  = mapa_peer(h_loc, q ^ 2);
    const uint32_t h_r3  = mapa_peer(h_loc, q ^ 3);

    cluster_sync_();

    for (int t = 0; t < SEQ; t++) {
        const float* __restrict__ Arow = g_A + ((size_t)t * 256 + b0) * GATE3;

        // prefetch precomputed activations (DRAM, consumed late)
        float a_g[4];
#pragma unroll
        for (int m = 0; m < 4; m++)
            a_g[m] = Arow[(m0 + m) * GATE3 + g * 256 + jg];
        float a_h0 = Arow[(r0 + 0) * GATE3 + 512 + jg2];
        float a_h1 = Arow[(r0 + 1) * GATE3 + 512 + jg2];

        // ---- phase 1: gate pre-activation h @ U_g (col jg, rows m0..m0+3) ----
        float ac0 = 0.f, ac1 = 0.f, ac2 = 0.f, ac3 = 0.f;
#pragma unroll 8
        for (int k = 0; k < 256; k++) {
            float u   = Ug[k * 64 + jj];
            float4 h4 = *reinterpret_cast<const float4*>(&hT[k * 8 + m0]);
            ac0 += h4.x * u;  ac1 += h4.y * u;
            ac2 += h4.z * u;  ac3 += h4.w * u;
        }

        if (g == 0) {
            float4 hj4 = *reinterpret_cast<const float4*>(&hT[jg * 8 + m0]);
            float4 rh;
            rh.x = sigmoidf_(a_g[0] + ac0) * hj4.x;
            rh.y = sigmoidf_(a_g[1] + ac1) * hj4.y;
            rh.z = sigmoidf_(a_g[2] + ac2) * hj4.z;
            rh.w = sigmoidf_(a_g[3] + ac3) * hj4.w;
            *reinterpret_cast<float4*>(&rhT[jg * 8 + m0]) = rh;
            st_cluster_v4(rh_r1, rh);
            st_cluster_v4(rh_r2, rh);
            st_cluster_v4(rh_r3, rh);
        } else {
            float4 zv;
            zv.x = sigmoidf_(a_g[0] + ac0);
            zv.y = sigmoidf_(a_g[1] + ac1);
            zv.z = sigmoidf_(a_g[2] + ac2);
            zv.w = sigmoidf_(a_g[3] + ac3);
            *reinterpret_cast<float4*>(&z_s[jj * 8 + m0]) = zv;
        }

        cluster_sync_();   // (A) full rh visible cluster-wide; z local

        // ---- phase 2: h_cand = tanh(a_h + (r*h) @ Uh), rows r0, r0+1 ----
        float ah0 = 0.f, ah1 = 0.f;
#pragma unroll 8
        for (int k = 0; k < 256; k++) {
            float u    = Uh_s[k * 64 + j2];
            float2 rh2 = *reinterpret_cast<const float2*>(&rhT[k * 8 + r0]);
            ah0 += rh2.x * u;
            ah1 += rh2.y * u;
        }

        float2 z2 = *reinterpret_cast<const float2*>(&z_s[j2 * 8 + r0]);
        float2 ho = *reinterpret_cast<const float2*>(&hT[jg2 * 8 + r0]);
        float hc0 = tanhf(a_h0 + ah0);
        float hc1 = tanhf(a_h1 + ah1);
        float2 hn;
        hn.x = z2.x * ho.x + (1.f - z2.x) * hc0;
        hn.y = z2.y * ho.y + (1.f - z2.y) * hc1;

        *reinterpret_cast<float2*>(&hT[jg2 * 8 + r0]) = hn;
        st_cluster_v2(h_r1, hn);
        st_cluster_v2(h_r2, hn);
        st_cluster_v2(h_r3, hn);

        cluster_sync_();   // (B) full updated h visible before next step
    }

    // ---- fused output: out[b0+r0+{0,1}, jg2] = h_last @ Wo[:, jg2] + bo ----
    float o0 = 0.f, o1 = 0.f;
#pragma unroll 8
    for (int k = 0; k < 256; k++) {
        float w   = Wo[k * 256 + jg2];
        float2 h2 = *reinterpret_cast<const float2*>(&hT[k * 8 + r0]);
        o0 += h2.x * w;
        o1 += h2.y * w;
    }
    float bj = bo[jg2];
    out[(b0 + r0 + 0) * 256 + jg2] = o0 + bj;
    out[(b0 + r0 + 1) * 256 + jg2] = o1 + bj;
}

// ---------------------------------------------------------------------------
// Launch
// ---------------------------------------------------------------------------
extern "C" void kernel_launch(void* const* d_in, const int* in_sizes, int n_in,
                              void* d_out, int out_size) {
    const float* x  = (const float*)d_in[0];
    const float* Wr = (const float*)d_in[1];
    const float* br = (const float*)d_in[2];
    const float* Wz = (const float*)d_in[3];
    const float* bz = (const float*)d_in[4];
    const float* Wh = (const float*)d_in[5];
    const float* bh = (const float*)d_in[6];
    const float* Wo = (const float*)d_in[7];
    const float* bo = (const float*)d_in[8];
    float* out = (float*)d_out;

    precompute_kernel<<<dim3(1024, 6), 256>>>(x, Wr, br, Wz, bz, Wh, bh);

    cudaFuncSetAttribute(gru_recurrence_kernel,
                         cudaFuncAttributeMaxDynamicSharedMemorySize, REC_SMEM_BYTES);

    cudaLaunchConfig_t cfg = {};
    cfg.gridDim  = dim3(128, 1, 1);
    cfg.blockDim = dim3(256, 1, 1);
    cfg.dynamicSmemBytes = REC_SMEM_BYTES;
    cfg.stream = 0;
    cudaLaunchAttribute attrs[1];
    attrs[0].id = cudaLaunchAttributeClusterDimension;
    attrs[0].val.clusterDim.x = 4;
    attrs[0].val.clusterDim.y = 1;
    attrs[0].val.clusterDim.z = 1;
    cfg.attrs = attrs;
    cfg.numAttrs = 1;
    cudaLaunchKernelEx(&cfg, gru_recurrence_kernel, Wr, Wz, Wh, Wo, bo, out);
}